// round 1
// baseline (speedup 1.0000x reference)
#include <cuda_runtime.h>
#include <math.h>

#define NT     1024
#define NWARP  32
#define BB     16
#define TT     32
#define INDIM  256
#define HDIM   512
#define RHEADS 4
#define WDIM   64
#define MDIM   512
#define DELTAF 1e-6f

// Link matrices: 16 x 512 x 512 fp32 = 16 MB, L2-resident scratch.
__device__ float g_link[(size_t)BB * MDIM * MDIM];

static __device__ __forceinline__ float warp_sum(float v) {
#pragma unroll
    for (int o = 16; o; o >>= 1) v += __shfl_down_sync(0xffffffffu, v, o);
    return v;
}
static __device__ __forceinline__ float warp_max(float v) {
#pragma unroll
    for (int o = 16; o; o >>= 1) v = fmaxf(v, __shfl_down_sync(0xffffffffu, v, o));
    return v;
}
static __device__ __forceinline__ float sigm(float x)  { return 1.0f / (1.0f + expf(-x)); }
static __device__ __forceinline__ float splus(float x) { return fmaxf(x, 0.0f) + log1pf(expf(-fabsf(x))); }

// Block-wide allreduce helpers (all 1024 threads must call).
static __device__ __forceinline__ float block_sum(float v, float* red) {
    int warp = threadIdx.x >> 5, lane = threadIdx.x & 31;
    v = warp_sum(v);
    if (!lane) red[warp] = v;
    __syncthreads();
    if (warp == 0) { float q = red[lane]; q = warp_sum(q); if (!lane) red[0] = q; }
    __syncthreads();
    float r = red[0];
    __syncthreads();
    return r;
}
static __device__ __forceinline__ float block_max(float v, float* red) {
    int warp = threadIdx.x >> 5, lane = threadIdx.x & 31;
    v = warp_max(v);
    if (!lane) red[warp] = v;
    __syncthreads();
    if (warp == 0) { float q = red[lane]; q = warp_max(q); if (!lane) red[0] = q; }
    __syncthreads();
    float r = red[0];
    __syncthreads();
    return r;
}
// In-place softmax over arr[0..511]; all threads call.
static __device__ void softmax512(float* arr, float* red) {
    int tid = threadIdx.x;
    float v  = (tid < MDIM) ? arr[tid] : -3.402823466e38f;
    float mx = block_max(v, red);
    float e  = (tid < MDIM) ? expf(arr[tid] - mx) : 0.0f;
    float s  = block_sum(e, red);
    if (tid < MDIM) arr[tid] = e / s;
    __syncthreads();
}

extern __shared__ float S[];

__global__ __launch_bounds__(NT, 1)
void dnc_kernel(const float* __restrict__ x,
                const float* __restrict__ W_ih, const float* __restrict__ b_ih,
                const float* __restrict__ W_hh, const float* __restrict__ b_hh,
                const float* __restrict__ W_out, const float* __restrict__ b_out,
                const float* __restrict__ W_int, const float* __restrict__ b_int,
                const float* __restrict__ W_mem, const float* __restrict__ b_mem,
                float* __restrict__ y_out)
{
    const int b    = blockIdx.x;
    const int tid  = threadIdx.x;
    const int warp = tid >> 5;
    const int lane = tid & 31;

    // ---- shared memory layout (all sizes multiples of 16 floats) ----
    float* mem   = S;              // 32768  mem[512][64]
    float* h     = mem + 32768;    // 512
    float* c     = h + 512;        // 512
    float* inp   = c + 512;        // 512 : [x_t(256), last_read(256)]
    float* gates = inp + 512;      // 2048 (alias: sort keys u64[512])
    float* outv  = gates + 2048;   // 512
    float* xi    = outv + 512;     // 480 (471 used)
    float* usage = xi + 480;       // 512
    float* wcw   = usage + 512;    // 512
    float* alloc = wcw + 512;      // 512
    float* wwv   = alloc + 512;    // 512 : write weights (old then new)
    float* prec  = wwv + 512;      // 512
    float* rw    = prec + 512;     // 2048 : read_w[4][512] (old then new)
    float* fwd   = rw + 2048;      // 2048
    float* bwd2  = fwd + 2048;     // 4096 : [2 parts][4][512]
    float* cw    = bwd2 + 4096;    // 2048 (alias: cumprod scan ping/pong 1024)
    float* rk    = cw + 2048;      // 256 : read keys (tanh'd) [4][64]
    float* wkey  = rk + 256;       // 64
    float* ers   = wkey + 64;      // 64
    float* wv    = ers + 64;       // 64
    float* sc    = wv + 64;        // 32 scalars
    float* red   = sc + 32;        // 32 reduce scratch
    // total 50656 floats = 202624 bytes
    unsigned long long* skey = (unsigned long long*)gates;

    // sc indices: 0 ikn, 1..4 irkn[4], 5..8 rstr[4], 9 wstr, 10..13 fg[4],
    //             14 ag, 15 wg, 16..27 modes[4][3]

    // ---- init state ----
    for (int i = tid; i < MDIM * WDIM; i += NT) mem[i] = 0.0f;
    for (int i = tid; i < 512; i += NT) { h[i] = 0.f; c[i] = 0.f; usage[i] = 0.f; prec[i] = 0.f; wwv[i] = 0.f; }
    for (int i = tid; i < 2048; i += NT) rw[i] = 0.0f;
    if (tid < 256) inp[256 + tid] = 0.0f;   // last_read
    {
        float4* L4 = (float4*)(g_link + (size_t)b * MDIM * MDIM);
        for (int i = tid; i < MDIM * MDIM / 4; i += NT) L4[i] = make_float4(0.f, 0.f, 0.f, 0.f);
    }
    __syncthreads();

    float* Lb = g_link + (size_t)b * MDIM * MDIM;

    for (int t = 0; t < TT; t++) {
        // ---- 1. load x_t ----
        const float* xt = x + ((size_t)b * TT + t) * INDIM;
        if (tid < 256) inp[tid] = xt[tid];
        __syncthreads();

        // ---- 2. gates GEMM: gates[o] = W_ih[o]·inp + W_hh[o]·h + b_ih + b_hh ----
        {
            const float4* vi = (const float4*)inp;
            const float4* vh = (const float4*)h;
            for (int o = warp; o < 4 * HDIM; o += NWARP) {
                const float4* wi = (const float4*)(W_ih + (size_t)o * 512);
                const float4* wh = (const float4*)(W_hh + (size_t)o * 512);
                float acc = 0.0f;
#pragma unroll
                for (int kk = 0; kk < 4; kk++) {
                    int k = lane + 32 * kk;
                    float4 a = wi[k], p = vi[k];
                    acc += a.x * p.x + a.y * p.y + a.z * p.z + a.w * p.w;
                    float4 bq = wh[k], q = vh[k];
                    acc += bq.x * q.x + bq.y * q.y + bq.z * q.z + bq.w * q.w;
                }
                acc = warp_sum(acc);
                if (!lane) gates[o] = acc + b_ih[o] + b_hh[o];
            }
        }
        __syncthreads();

        // ---- 3. LSTM cell ----
        if (tid < HDIM) {
            float gi = sigm(gates[tid]);
            float gf = sigm(gates[HDIM + tid]);
            float gg = tanhf(gates[2 * HDIM + tid]);
            float go = sigm(gates[3 * HDIM + tid]);
            float cn = gf * c[tid] + gi * gg;
            c[tid] = cn;
            h[tid] = go * tanhf(cn);
        }
        __syncthreads();

        // ---- 4. out = h@W_out^T + b_out ; xi = h@W_int^T + b_int ----
        {
            const float4* vh = (const float4*)h;
            for (int o = warp; o < 983; o += NWARP) {  // 512 out + 471 xi
                const float* wr = (o < 512) ? (W_out + (size_t)o * 512)
                                            : (W_int + (size_t)(o - 512) * 512);
                const float4* w4 = (const float4*)wr;
                float acc = 0.0f;
#pragma unroll
                for (int kk = 0; kk < 4; kk++) {
                    int k = lane + 32 * kk;
                    float4 a = w4[k], p = vh[k];
                    acc += a.x * p.x + a.y * p.y + a.z * p.z + a.w * p.w;
                }
                acc = warp_sum(acc);
                if (!lane) {
                    if (o < 512) outv[o] = acc + b_out[o];
                    else         xi[o - 512] = acc + b_int[o - 512];
                }
            }
        }
        __syncthreads();

        // ---- 5. parse interface ----
        if (tid < 256)       rk[tid]         = tanhf(xi[tid]);
        else if (tid < 320)  wkey[tid - 256] = tanhf(xi[260 + (tid - 256)]);
        else if (tid < 384)  ers[tid - 320]  = sigm(xi[325 + (tid - 320)]);
        else if (tid < 448)  wv[tid - 384]   = tanhf(xi[389 + (tid - 384)]);
        else if (tid < 452)  sc[5 + (tid - 448)]  = splus(xi[256 + (tid - 448)]);  // read_str
        else if (tid == 452) sc[9]  = splus(xi[324]);                              // write_str
        else if (tid < 457)  sc[10 + (tid - 453)] = sigm(xi[453 + (tid - 453)]);   // free gates
        else if (tid == 457) sc[14] = sigm(xi[457]);                               // alloc gate
        else if (tid == 458) sc[15] = sigm(xi[458]);                               // write gate
        else if (tid < 463) {                                                       // read modes
            int r = tid - 459;
            float a = xi[459 + 3 * r], bm = xi[460 + 3 * r], cm = xi[461 + 3 * r];
            float mx = fmaxf(a, fmaxf(bm, cm));
            float ea = expf(a - mx), eb = expf(bm - mx), ec = expf(cm - mx);
            float s = ea + eb + ec;
            sc[16 + 3 * r] = ea / s; sc[17 + 3 * r] = eb / s; sc[18 + 3 * r] = ec / s;
        }
        __syncthreads();

        // ---- 6. key norms (warps 0..4) + usage update ----
        if (warp < 5) {
            const float* kp = (warp == 0) ? wkey : (rk + (warp - 1) * 64);
            float a = kp[lane], bq = kp[lane + 32];
            float ss = warp_sum(a * a + bq * bq);
            if (!lane) sc[warp] = 1.0f / (sqrtf(ss) + DELTAF);  // sc[0]=ikn, sc[1..4]=irkn
        }
        if (tid < MDIM) {
            float u = usage[tid];
            u = u + (1.0f - u) * wwv[tid];          // old write_w
            float psi = 1.0f;
#pragma unroll
            for (int r = 0; r < RHEADS; r++) psi *= (1.0f - sc[10 + r] * rw[r * MDIM + tid]);
            usage[tid] = u * psi;
        }
        __syncthreads();

        // ---- 7. write content weights: cosine(write_key, mem_old) * wstr ----
        {
            float ikn = sc[0], wstr = sc[9];
            for (int m = warp; m < MDIM; m += NWARP) {
                float a = mem[m * 64 + lane], bq = mem[m * 64 + lane + 32];
                float ss = a * a + bq * bq;
                float dk = a * wkey[lane] + bq * wkey[lane + 32];
#pragma unroll
                for (int o = 16; o; o >>= 1) {
                    ss += __shfl_down_sync(0xffffffffu, ss, o);
                    dk += __shfl_down_sync(0xffffffffu, dk, o);
                }
                if (!lane) {
                    float im = 1.0f / (sqrtf(ss) + DELTAF);
                    wcw[m] = dk * im * ikn * wstr;
                }
            }
        }
        __syncthreads();
        softmax512(wcw, red);

        // ---- 8. allocation: stable sort by (u, idx), exclusive cumprod ----
        if (tid < MDIM) {
            float u = DELTAF + (1.0f - DELTAF) * usage[tid];
            skey[tid] = ((unsigned long long)__float_as_uint(u) << 32) | (unsigned)tid;
        }
        __syncthreads();
        for (int k = 2; k <= MDIM; k <<= 1) {
            for (int j = k >> 1; j > 0; j >>= 1) {
                if (tid < MDIM) {
                    int ixj = tid ^ j;
                    if (ixj > tid) {
                        bool up = ((tid & k) == 0);
                        unsigned long long A = skey[tid], Bk = skey[ixj];
                        if ((A > Bk) == up) { skey[tid] = Bk; skey[ixj] = A; }
                    }
                }
                __syncthreads();
            }
        }
        {   // exclusive cumprod of sorted u via Hillis-Steele scan (ping/pong in cw)
            float* sp = cw; float* sq = cw + 512;
            if (tid < MDIM) {
                float su_prev = (tid == 0) ? 1.0f
                              : __uint_as_float((unsigned)(skey[tid - 1] >> 32));
                sp[tid] = su_prev;
            }
            __syncthreads();
            for (int off = 1; off < MDIM; off <<= 1) {
                if (tid < MDIM) sq[tid] = sp[tid] * ((tid >= off) ? sp[tid - off] : 1.0f);
                __syncthreads();
                float* tmp = sp; sp = sq; sq = tmp;
            }
            if (tid < MDIM) {
                unsigned long long kk = skey[tid];
                unsigned idx = (unsigned)(kk & 0xffffffffu);
                float su = __uint_as_float((unsigned)(kk >> 32));
                alloc[idx] = (1.0f - su) * sp[tid];
            }
        }
        __syncthreads();

        // ---- 9. new write weights ----
        if (tid < MDIM) {
            float ag = sc[14], wg = sc[15];
            wwv[tid] = wg * (ag * alloc[tid] + (1.0f - ag) * wcw[tid]);
        }
        __syncthreads();
        float sumww = block_sum((tid < MDIM) ? wwv[tid] : 0.0f, red);

        // ---- 10. memory update ----
        for (int i = tid; i < MDIM * WDIM; i += NT) {
            int m = i >> 6, w_ = i & 63;
            float wwm = wwv[m];
            mem[i] = mem[i] * (1.0f - wwm * ers[w_]) + wwm * wv[w_];
        }
        __syncthreads();

        // ---- 11. link pass A: L_new + fwd (fused) ----
        {
            const float4* ww4 = (const float4*)wwv;
            const float4* pr4 = (const float4*)prec;
            const float4* r0b = (const float4*)(rw);
            const float4* r1b = (const float4*)(rw + MDIM);
            const float4* r2b = (const float4*)(rw + 2 * MDIM);
            const float4* r3b = (const float4*)(rw + 3 * MDIM);
            for (int i = warp; i < MDIM; i += NWARP) {
                float wwi = wwv[i];
                float f0 = 0.f, f1 = 0.f, f2 = 0.f, f3 = 0.f;
                float4* row = (float4*)(Lb + (size_t)i * MDIM);
#pragma unroll
                for (int kk = 0; kk < 4; kk++) {
                    int k = lane + 32 * kk;
                    float4 l  = row[k];
                    float4 wj = ww4[k], pj = pr4[k];
                    int j0 = k << 2;
                    float n0 = (j0     == i) ? 0.f : (1.f - wwi - wj.x) * l.x + wwi * pj.x;
                    float n1 = (j0 + 1 == i) ? 0.f : (1.f - wwi - wj.y) * l.y + wwi * pj.y;
                    float n2 = (j0 + 2 == i) ? 0.f : (1.f - wwi - wj.z) * l.z + wwi * pj.z;
                    float n3 = (j0 + 3 == i) ? 0.f : (1.f - wwi - wj.w) * l.w + wwi * pj.w;
                    row[k] = make_float4(n0, n1, n2, n3);
                    float4 r0 = r0b[k], r1 = r1b[k], r2 = r2b[k], r3 = r3b[k];
                    f0 += n0 * r0.x + n1 * r0.y + n2 * r0.z + n3 * r0.w;
                    f1 += n0 * r1.x + n1 * r1.y + n2 * r1.z + n3 * r1.w;
                    f2 += n0 * r2.x + n1 * r2.y + n2 * r2.z + n3 * r2.w;
                    f3 += n0 * r3.x + n1 * r3.y + n2 * r3.z + n3 * r3.w;
                }
                f0 = warp_sum(f0); f1 = warp_sum(f1); f2 = warp_sum(f2); f3 = warp_sum(f3);
                if (!lane) {
                    fwd[i] = f0; fwd[MDIM + i] = f1; fwd[2 * MDIM + i] = f2; fwd[3 * MDIM + i] = f3;
                }
            }
        }
        __syncthreads();

        // ---- 12. link pass B: bwd (split i-range over 2 halves of the block) ----
        {
            int part = tid >> 9;       // 0 or 1
            int j = tid & 511;
            float b0 = 0.f, b1 = 0.f, b2 = 0.f, b3 = 0.f;
            int i0 = part * 256;
#pragma unroll 4
            for (int i = i0; i < i0 + 256; i++) {
                float l = Lb[(size_t)i * MDIM + j];
                b0 += rw[i] * l;
                b1 += rw[MDIM + i] * l;
                b2 += rw[2 * MDIM + i] * l;
                b3 += rw[3 * MDIM + i] * l;
            }
            float* bp = bwd2 + part * 2048;
            bp[j] = b0; bp[512 + j] = b1; bp[1024 + j] = b2; bp[1536 + j] = b3;
        }
        __syncthreads();

        // ---- 13. precedence update + read content weights (new mem) ----
        if (tid < MDIM) prec[tid] = (1.0f - sumww) * prec[tid] + wwv[tid];
        for (int m = warp; m < MDIM; m += NWARP) {
            float a = mem[m * 64 + lane], bq = mem[m * 64 + lane + 32];
            float ss = a * a + bq * bq;
            float d0 = a * rk[lane]       + bq * rk[lane + 32];
            float d1 = a * rk[64 + lane]  + bq * rk[96 + lane];
            float d2 = a * rk[128 + lane] + bq * rk[160 + lane];
            float d3 = a * rk[192 + lane] + bq * rk[224 + lane];
#pragma unroll
            for (int o = 16; o; o >>= 1) {
                ss += __shfl_down_sync(0xffffffffu, ss, o);
                d0 += __shfl_down_sync(0xffffffffu, d0, o);
                d1 += __shfl_down_sync(0xffffffffu, d1, o);
                d2 += __shfl_down_sync(0xffffffffu, d2, o);
                d3 += __shfl_down_sync(0xffffffffu, d3, o);
            }
            if (!lane) {
                float im = 1.0f / (sqrtf(ss) + DELTAF);
                cw[m]            = d0 * im * sc[1] * sc[5];
                cw[MDIM + m]     = d1 * im * sc[2] * sc[6];
                cw[2 * MDIM + m] = d2 * im * sc[3] * sc[7];
                cw[3 * MDIM + m] = d3 * im * sc[4] * sc[8];
            }
        }
        __syncthreads();
        for (int r = 0; r < RHEADS; r++) softmax512(cw + r * MDIM, red);

        // ---- 14. new read weights ----
        for (int q = tid; q < RHEADS * MDIM; q += NT) {
            int r = q >> 9, mm = q & 511;
            float bsum = bwd2[r * 512 + mm] + bwd2[2048 + r * 512 + mm];
            rw[q] = sc[16 + 3 * r] * bsum + sc[17 + 3 * r] * fwd[q] + sc[18 + 3 * r] * cw[q];
        }
        __syncthreads();

        // ---- 15. read vectors -> last_read (inp[256..]) ----
        if (tid < RHEADS * WDIM) {
            int r = tid >> 6, w_ = tid & 63;
            float acc = 0.0f;
#pragma unroll 8
            for (int m = 0; m < MDIM; m++) acc += rw[r * MDIM + m] * mem[m * 64 + w_];
            inp[256 + tid] = acc;
        }
        __syncthreads();

        // ---- 16. output: y = [out, read_vecs] @ W_mem^T + b_mem ----
        {
            float* yrow = y_out + ((size_t)b * TT + t) * INDIM;
            const float4* v1 = (const float4*)outv;
            const float4* v2 = (const float4*)(inp + 256);
            for (int o = warp; o < INDIM; o += NWARP) {
                const float4* w4 = (const float4*)(W_mem + (size_t)o * 768);
                float acc = 0.0f;
#pragma unroll
                for (int kk = 0; kk < 6; kk++) {
                    int k = lane + 32 * kk;
                    float4 a = w4[k];
                    float4 p = (k < 128) ? v1[k] : v2[k - 128];
                    acc += a.x * p.x + a.y * p.y + a.z * p.z + a.w * p.w;
                }
                acc = warp_sum(acc);
                if (!lane) yrow[o] = acc + b_mem[o];
            }
        }
        __syncthreads();
    }
}

extern "C" void kernel_launch(void* const* d_in, const int* in_sizes, int n_in,
                              void* d_out, int out_size) {
    (void)in_sizes; (void)n_in; (void)out_size;
    const int SMEM_BYTES = 50656 * 4;  // 202624
    cudaFuncSetAttribute(dnc_kernel, cudaFuncAttributeMaxDynamicSharedMemorySize, SMEM_BYTES);
    dnc_kernel<<<BB, NT, SMEM_BYTES>>>(
        (const float*)d_in[0],
        (const float*)d_in[1], (const float*)d_in[2],
        (const float*)d_in[3], (const float*)d_in[4],
        (const float*)d_in[5], (const float*)d_in[6],
        (const float*)d_in[7], (const float*)d_in[8],
        (const float*)d_in[9], (const float*)d_in[10],
        (float*)d_out);
}

// round 5
// speedup vs baseline: 1.0051x; 1.0051x over previous
#include <cuda_runtime.h>
#include <math.h>
#include <stdint.h>

#define NT     1024
#define NWARP  32
#define BB     16
#define TT     32
#define INDIM  256
#define HDIM   512
#define RHEADS 4
#define WDIM   64
#define MDIM   512
#define DELTAF 1e-6f

typedef unsigned long long ull;

// Link matrices: 16 x 512 x 512 fp32 = 16 MB, L2-resident scratch.
__device__ float g_link[(size_t)BB * MDIM * MDIM];

// ---- packed f32x2 helpers (two independent fp32 ops per instruction) ----
static __device__ __forceinline__ ull pk2(float a, float b) {
    ull r; asm("mov.b64 %0,{%1,%2};" : "=l"(r) : "f"(a), "f"(b)); return r;
}
static __device__ __forceinline__ float2 upk2(ull v) {
    float2 f; asm("mov.b64 {%0,%1},%2;" : "=f"(f.x), "=f"(f.y) : "l"(v)); return f;
}
static __device__ __forceinline__ ull add2(ull a, ull b) {
    ull d; asm("add.rn.f32x2 %0,%1,%2;" : "=l"(d) : "l"(a), "l"(b)); return d;
}
static __device__ __forceinline__ ull mul2(ull a, ull b) {
    ull d; asm("mul.rn.f32x2 %0,%1,%2;" : "=l"(d) : "l"(a), "l"(b)); return d;
}
static __device__ __forceinline__ ull fma2(ull a, ull b, ull c) {
    ull d; asm("fma.rn.f32x2 %0,%1,%2,%3;" : "=l"(d) : "l"(a), "l"(b), "l"(c)); return d;
}

static __device__ __forceinline__ float warp_sum(float v) {
#pragma unroll
    for (int o = 16; o; o >>= 1) v += __shfl_down_sync(0xffffffffu, v, o);
    return v;
}
static __device__ __forceinline__ float sigm(float x)  { return 1.0f / (1.0f + expf(-x)); }
static __device__ __forceinline__ float splus(float x) { return fmaxf(x, 0.0f) + log1pf(expf(-fabsf(x))); }

static __device__ __forceinline__ float block_sum(float v, float* red) {
    int warp = threadIdx.x >> 5, lane = threadIdx.x & 31;
    v = warp_sum(v);
    if (!lane) red[warp] = v;
    __syncthreads();
    if (warp == 0) { float q = red[lane]; q = warp_sum(q); if (!lane) red[0] = q; }
    __syncthreads();
    float r = red[0];
    __syncthreads();
    return r;
}

// Single-warp softmax over arr[0..511]; only the executing warp participates.
static __device__ __forceinline__ void warp_softmax512(float* arr) {
    int lane = threadIdx.x & 31;
    float v[16];
    float mx = -3.402823466e38f;
#pragma unroll
    for (int k = 0; k < 16; k++) { v[k] = arr[lane + 32 * k]; mx = fmaxf(mx, v[k]); }
#pragma unroll
    for (int o = 16; o; o >>= 1) mx = fmaxf(mx, __shfl_xor_sync(0xffffffffu, mx, o));
    float s = 0.0f;
#pragma unroll
    for (int k = 0; k < 16; k++) { v[k] = expf(v[k] - mx); s += v[k]; }
#pragma unroll
    for (int o = 16; o; o >>= 1) s += __shfl_xor_sync(0xffffffffu, s, o);
    float inv = 1.0f / s;
#pragma unroll
    for (int k = 0; k < 16; k++) arr[lane + 32 * k] = v[k] * inv;
}

extern __shared__ float S[];

__global__ __launch_bounds__(NT, 1)
void dnc_kernel(const float* __restrict__ x,
                const float* __restrict__ W_ih, const float* __restrict__ b_ih,
                const float* __restrict__ W_hh, const float* __restrict__ b_hh,
                const float* __restrict__ W_out, const float* __restrict__ b_out,
                const float* __restrict__ W_int, const float* __restrict__ b_int,
                const float* __restrict__ W_mem, const float* __restrict__ b_mem,
                float* __restrict__ y_out)
{
    const int b    = blockIdx.x;
    const int tid  = threadIdx.x;
    const int warp = tid >> 5;
    const int lane = tid & 31;

    // ---- shared memory layout (all offsets multiples of 16 floats) ----
    float* mem   = S;              // 32768  mem[512][64]
    float* h     = mem + 32768;    // 512
    float* c     = h + 512;        // 512
    float* inp   = c + 512;        // 512 : [x_t(256), last_read(256)]
    float* gates = inp + 512;      // 2048 (alias: sort keys u64[512] in first 1024; nww in [1024..1535])
    float* outv  = gates + 2048;   // 512
    float* xi    = outv + 512;     // 480 (471 used)
    float* usage = xi + 480;       // 512
    float* wcw   = usage + 512;    // 512
    float* alloc = wcw + 512;      // 512
    float* wwv   = alloc + 512;    // 512
    float* prec  = wwv + 512;      // 512
    float* rw    = prec + 512;     // 2048 : read_w[4][512]
    float* fwd   = rw + 2048;      // 2048
    float* bwd   = fwd + 2048;     // 2048
    float* rwp01 = bwd + 2048;     // 1024 : float2[512] = (rw0[i], rw1[i])
    float* rwp23 = rwp01 + 1024;   // 1024 : float2[512] = (rw2[i], rw3[i])
    float* cw    = rwp23 + 1024;   // 2048 (alias: cumprod scan ping/pong 1024)
    float* rk    = cw + 2048;      // 256 : read keys (tanh'd) [4][64]
    float* wkey  = rk + 256;       // 64
    float* ers   = wkey + 64;      // 64
    float* wv    = ers + 64;       // 64
    float* sc    = wv + 64;        // 32 scalars
    float* red   = sc + 32;        // 32 reduce scratch
    // total 50656 floats = 202624 bytes
    ull*   skey = (ull*)gates;          // sort keys (gates[0..1023])
    float* nww  = gates + 1024;         // -wwv (gates[1024..1535])

    // sc: 0 ikn, 1..4 irkn[4], 5..8 rstr[4], 9 wstr, 10..13 fg[4], 14 ag, 15 wg, 16..27 modes

    // ---- init state ----
    for (int i = tid; i < MDIM * WDIM; i += NT) mem[i] = 0.0f;
    for (int i = tid; i < 512; i += NT) { h[i] = 0.f; c[i] = 0.f; usage[i] = 0.f; prec[i] = 0.f; wwv[i] = 0.f; }
    for (int i = tid; i < 2048; i += NT) rw[i] = 0.0f;
    if (tid < 256) inp[256 + tid] = 0.0f;   // last_read
    {
        float4* L4 = (float4*)(g_link + (size_t)b * MDIM * MDIM);
        for (int i = tid; i < MDIM * MDIM / 4; i += NT) L4[i] = make_float4(0.f, 0.f, 0.f, 0.f);
    }
    __syncthreads();

    float* Lb = g_link + (size_t)b * MDIM * MDIM;

    for (int t = 0; t < TT; t++) {
        // ---- 1. load x_t ----
        const float* xt = x + ((size_t)b * TT + t) * INDIM;
        if (tid < 256) inp[tid] = xt[tid];
        __syncthreads();

        // ---- 2. gates GEMV: packed f32x2 ----
        {
            const ulonglong2* vi = (const ulonglong2*)inp;
            const ulonglong2* vh = (const ulonglong2*)h;
            for (int o = warp; o < 4 * HDIM; o += NWARP) {
                const ulonglong2* wi = (const ulonglong2*)(W_ih + (size_t)o * 512);
                const ulonglong2* wh = (const ulonglong2*)(W_hh + (size_t)o * 512);
                ull acc = 0;
#pragma unroll
                for (int kk = 0; kk < 4; kk++) {
                    int k = lane + (kk << 5);
                    ulonglong2 a = wi[k], p = vi[k];
                    acc = fma2(a.x, p.x, acc);
                    acc = fma2(a.y, p.y, acc);
                    ulonglong2 bq = wh[k], q = vh[k];
                    acc = fma2(bq.x, q.x, acc);
                    acc = fma2(bq.y, q.y, acc);
                }
                float2 f = upk2(acc);
                float s = warp_sum(f.x + f.y);
                if (!lane) gates[o] = s + b_ih[o] + b_hh[o];
            }
        }
        __syncthreads();

        // ---- 3. LSTM cell ----
        if (tid < HDIM) {
            float gi = sigm(gates[tid]);
            float gf = sigm(gates[HDIM + tid]);
            float gg = tanhf(gates[2 * HDIM + tid]);
            float go = sigm(gates[3 * HDIM + tid]);
            float cn = gf * c[tid] + gi * gg;
            c[tid] = cn;
            h[tid] = go * tanhf(cn);
        }
        __syncthreads();

        // ---- 4. out/xi GEMV: packed f32x2 ----
        {
            const ulonglong2* vh = (const ulonglong2*)h;
            for (int o = warp; o < 983; o += NWARP) {
                const float* wr = (o < 512) ? (W_out + (size_t)o * 512)
                                            : (W_int + (size_t)(o - 512) * 512);
                const ulonglong2* w2 = (const ulonglong2*)wr;
                ull acc = 0;
#pragma unroll
                for (int kk = 0; kk < 4; kk++) {
                    int k = lane + (kk << 5);
                    ulonglong2 a = w2[k], p = vh[k];
                    acc = fma2(a.x, p.x, acc);
                    acc = fma2(a.y, p.y, acc);
                }
                float2 f = upk2(acc);
                float s = warp_sum(f.x + f.y);
                if (!lane) {
                    if (o < 512) outv[o] = s + b_out[o];
                    else         xi[o - 512] = s + b_int[o - 512];
                }
            }
        }
        __syncthreads();

        // ---- 5. parse interface ----
        if (tid < 256)       rk[tid]         = tanhf(xi[tid]);
        else if (tid < 320)  wkey[tid - 256] = tanhf(xi[260 + (tid - 256)]);
        else if (tid < 384)  ers[tid - 320]  = sigm(xi[325 + (tid - 320)]);
        else if (tid < 448)  wv[tid - 384]   = tanhf(xi[389 + (tid - 384)]);
        else if (tid < 452)  sc[5 + (tid - 448)]  = splus(xi[256 + (tid - 448)]);
        else if (tid == 452) sc[9]  = splus(xi[324]);
        else if (tid < 457)  sc[10 + (tid - 453)] = sigm(xi[453 + (tid - 453)]);
        else if (tid == 457) sc[14] = sigm(xi[457]);
        else if (tid == 458) sc[15] = sigm(xi[458]);
        else if (tid < 463) {
            int r = tid - 459;
            float a = xi[459 + 3 * r], bm = xi[460 + 3 * r], cm = xi[461 + 3 * r];
            float mx = fmaxf(a, fmaxf(bm, cm));
            float ea = expf(a - mx), eb = expf(bm - mx), ec = expf(cm - mx);
            float s = ea + eb + ec;
            sc[16 + 3 * r] = ea / s; sc[17 + 3 * r] = eb / s; sc[18 + 3 * r] = ec / s;
        }
        __syncthreads();

        // ---- 6. key norms + usage update ----
        if (warp < 5) {
            const float* kp = (warp == 0) ? wkey : (rk + (warp - 1) * 64);
            float a = kp[lane], bq = kp[lane + 32];
            float ss = warp_sum(a * a + bq * bq);
            if (!lane) sc[warp] = 1.0f / (sqrtf(ss) + DELTAF);
        }
        if (tid < MDIM) {
            float u = usage[tid];
            u = u + (1.0f - u) * wwv[tid];          // old write_w
            float psi = 1.0f;
#pragma unroll
            for (int r = 0; r < RHEADS; r++) psi *= (1.0f - sc[10 + r] * rw[r * MDIM + tid]);
            usage[tid] = u * psi;
        }
        __syncthreads();

        // ---- 7. write content weights: cosine(write_key, mem_old) * wstr ----
        {
            float ikn = sc[0], wstr = sc[9];
            for (int m = warp; m < MDIM; m += NWARP) {
                float a = mem[m * 64 + lane], bq = mem[m * 64 + lane + 32];
                float ss = a * a + bq * bq;
                float dk = a * wkey[lane] + bq * wkey[lane + 32];
#pragma unroll
                for (int o = 16; o; o >>= 1) {
                    ss += __shfl_down_sync(0xffffffffu, ss, o);
                    dk += __shfl_down_sync(0xffffffffu, dk, o);
                }
                if (!lane) {
                    float im = 1.0f / (sqrtf(ss) + DELTAF);
                    wcw[m] = dk * im * ikn * wstr;
                }
            }
        }
        __syncthreads();
        if (warp == 0) warp_softmax512(wcw);
        __syncthreads();

        // ---- 8. allocation: stable bitonic sort + exclusive cumprod scan ----
        if (tid < MDIM) {
            float u = DELTAF + (1.0f - DELTAF) * usage[tid];
            skey[tid] = ((ull)__float_as_uint(u) << 32) | (unsigned)tid;
        }
        __syncthreads();
        for (int k = 2; k <= MDIM; k <<= 1) {
            for (int j = k >> 1; j > 0; j >>= 1) {
                if (tid < MDIM) {
                    int ixj = tid ^ j;
                    if (ixj > tid) {
                        bool up = ((tid & k) == 0);
                        ull A = skey[tid], Bk = skey[ixj];
                        if ((A > Bk) == up) { skey[tid] = Bk; skey[ixj] = A; }
                    }
                }
                __syncthreads();
            }
        }
        {   // exclusive cumprod of sorted u via Hillis-Steele scan (ping/pong in cw)
            float* sp = cw; float* sq = cw + 512;
            if (tid < MDIM) {
                float su_prev = (tid == 0) ? 1.0f
                              : __uint_as_float((unsigned)(skey[tid - 1] >> 32));
                sp[tid] = su_prev;
            }
            __syncthreads();
            for (int off = 1; off < MDIM; off <<= 1) {
                if (tid < MDIM) sq[tid] = sp[tid] * ((tid >= off) ? sp[tid - off] : 1.0f);
                __syncthreads();
                float* tmp = sp; sp = sq; sq = tmp;
            }
            if (tid < MDIM) {
                ull kk = skey[tid];
                unsigned idx = (unsigned)(kk & 0xffffffffu);
                float su = __uint_as_float((unsigned)(kk >> 32));
                alloc[idx] = (1.0f - su) * sp[tid];
            }
        }
        __syncthreads();

        // ---- 9. new write weights + negated copy for link pass ----
        if (tid < MDIM) {
            float ag = sc[14], wg = sc[15];
            float w_ = wg * (ag * alloc[tid] + (1.0f - ag) * wcw[tid]);
            wwv[tid] = w_;
            nww[tid] = -w_;
        }
        __syncthreads();
        float sumww = block_sum((tid < MDIM) ? wwv[tid] : 0.0f, red);

        // ---- 10. memory update ----
        for (int i = tid; i < MDIM * WDIM; i += NT) {
            int m = i >> 6, w_ = i & 63;
            float wwm = wwv[m];
            mem[i] = mem[i] * (1.0f - wwm * ers[w_]) + wwm * wv[w_];
        }
        __syncthreads();

        // ---- 11. link pass A: L_new + fwd, packed f32x2, diagonal post-fix ----
        // Unmasked update: n = ((1-wwi) - wwj)*l + wwi*prec_j.  Old L[i][i] == 0,
        // so diagonal contribution is exactly wwi*prec[i]; subtract it from fwd
        // and store L[i][i] = 0 afterwards.
        {
            const ulonglong2* nw2 = (const ulonglong2*)nww;
            const ulonglong2* pr2 = (const ulonglong2*)prec;
            const ulonglong2* r0b = (const ulonglong2*)(rw);
            const ulonglong2* r1b = (const ulonglong2*)(rw + MDIM);
            const ulonglong2* r2b = (const ulonglong2*)(rw + 2 * MDIM);
            const ulonglong2* r3b = (const ulonglong2*)(rw + 3 * MDIM);
            for (int i = warp; i < MDIM; i += NWARP) {
                float wwi = wwv[i];
                ull wwi2 = pk2(wwi, wwi);
                ull omw2 = pk2(1.0f - wwi, 1.0f - wwi);
                ull f0 = 0, f1 = 0, f2 = 0, f3 = 0;
                ulonglong2* row = (ulonglong2*)(Lb + (size_t)i * MDIM);
#pragma unroll
                for (int kk = 0; kk < 4; kk++) {
                    int k = lane + (kk << 5);
                    ulonglong2 l  = row[k];
                    ulonglong2 nj = nw2[k], pj = pr2[k];
                    ull c0 = add2(omw2, nj.x);
                    ull c1 = add2(omw2, nj.y);
                    ull n0 = fma2(wwi2, pj.x, mul2(c0, l.x));
                    ull n1 = fma2(wwi2, pj.y, mul2(c1, l.y));
                    ulonglong2 nout; nout.x = n0; nout.y = n1;
                    row[k] = nout;
                    ulonglong2 r0 = r0b[k]; f0 = fma2(n0, r0.x, f0); f0 = fma2(n1, r0.y, f0);
                    ulonglong2 r1 = r1b[k]; f1 = fma2(n0, r1.x, f1); f1 = fma2(n1, r1.y, f1);
                    ulonglong2 r2 = r2b[k]; f2 = fma2(n0, r2.x, f2); f2 = fma2(n1, r2.y, f2);
                    ulonglong2 r3 = r3b[k]; f3 = fma2(n0, r3.x, f3); f3 = fma2(n1, r3.y, f3);
                }
                float2 a0 = upk2(f0), a1 = upk2(f1), a2 = upk2(f2), a3 = upk2(f3);
                float s0 = warp_sum(a0.x + a0.y);
                float s1 = warp_sum(a1.x + a1.y);
                float s2 = warp_sum(a2.x + a2.y);
                float s3 = warp_sum(a3.x + a3.y);
                if (!lane) {
                    float corr = wwi * prec[i];   // OLD prec
                    fwd[i]            = s0 - corr * rw[i];
                    fwd[MDIM + i]     = s1 - corr * rw[MDIM + i];
                    fwd[2 * MDIM + i] = s2 - corr * rw[2 * MDIM + i];
                    fwd[3 * MDIM + i] = s3 - corr * rw[3 * MDIM + i];
                    Lb[(size_t)i * MDIM + i] = 0.0f;
                }
            }
        }
        // prepare pass B inputs (bwd zero + OLD-rw head pairs)
        for (int q = tid; q < 2048; q += NT) bwd[q] = 0.0f;
        if (tid < MDIM) {
            ((float2*)rwp01)[tid] = make_float2(rw[tid], rw[MDIM + tid]);
            ((float2*)rwp23)[tid] = make_float2(rw[2 * MDIM + tid], rw[3 * MDIM + tid]);
        }
        __syncthreads();   // L rows + bwd/pairs visible block-wide

        // ---- 12. link pass B: bwd[h][j] = sum_i rw_h[i] * L[i][j] ----
        // warp = (i-group 0..7) x (j-block 0..3); lane covers 4 consecutive j.
        {
            int ig = warp >> 2, jb = warp & 3;
            const float* Lbase = Lb + (size_t)(ig * 64) * MDIM + jb * 128 + lane * 4;
            const ull* rp01 = (const ull*)rwp01 + ig * 64;
            const ull* rp23 = (const ull*)rwp23 + ig * 64;
            ull b01[4] = {0, 0, 0, 0}, b23[4] = {0, 0, 0, 0};
#pragma unroll 4
            for (int ii = 0; ii < 64; ii++) {
                float4 l = *(const float4*)(Lbase + (size_t)ii * MDIM);
                ull r01 = rp01[ii], r23 = rp23[ii];
                ull l0 = pk2(l.x, l.x), l1 = pk2(l.y, l.y);
                ull l2 = pk2(l.z, l.z), l3 = pk2(l.w, l.w);
                b01[0] = fma2(l0, r01, b01[0]); b01[1] = fma2(l1, r01, b01[1]);
                b01[2] = fma2(l2, r01, b01[2]); b01[3] = fma2(l3, r01, b01[3]);
                b23[0] = fma2(l0, r23, b23[0]); b23[1] = fma2(l1, r23, b23[1]);
                b23[2] = fma2(l2, r23, b23[2]); b23[3] = fma2(l3, r23, b23[3]);
            }
            int jbase = jb * 128 + lane * 4;
#pragma unroll
            for (int e = 0; e < 4; e++) {
                float2 v01 = upk2(b01[e]), v23 = upk2(b23[e]);
                atomicAdd(&bwd[jbase + e],            v01.x);
                atomicAdd(&bwd[MDIM + jbase + e],     v01.y);
                atomicAdd(&bwd[2 * MDIM + jbase + e], v23.x);
                atomicAdd(&bwd[3 * MDIM + jbase + e], v23.y);
            }
        }

        // ---- 13. precedence update + read content weights (new mem) ----
        if (tid < MDIM) prec[tid] = (1.0f - sumww) * prec[tid] + wwv[tid];
        for (int m = warp; m < MDIM; m += NWARP) {
            float a = mem[m * 64 + lane], bq = mem[m * 64 + lane + 32];
            float ss = a * a + bq * bq;
            float d0 = a * rk[lane]       + bq * rk[lane + 32];
            float d1 = a * rk[64 + lane]  + bq * rk[96 + lane];
            float d2 = a * rk[128 + lane] + bq * rk[160 + lane];
            float d3 = a * rk[192 + lane] + bq * rk[224 + lane];
#pragma unroll
            for (int o = 16; o; o >>= 1) {
                ss += __shfl_down_sync(0xffffffffu, ss, o);
                d0 += __shfl_down_sync(0xffffffffu, d0, o);
                d1 += __shfl_down_sync(0xffffffffu, d1, o);
                d2 += __shfl_down_sync(0xffffffffu, d2, o);
                d3 += __shfl_down_sync(0xffffffffu, d3, o);
            }
            if (!lane) {
                float im = 1.0f / (sqrtf(ss) + DELTAF);
                cw[m]            = d0 * im * sc[1] * sc[5];
                cw[MDIM + m]     = d1 * im * sc[2] * sc[6];
                cw[2 * MDIM + m] = d2 * im * sc[3] * sc[7];
                cw[3 * MDIM + m] = d3 * im * sc[4] * sc[8];
            }
        }
        __syncthreads();
        if (warp < 4) warp_softmax512(cw + warp * MDIM);
        __syncthreads();

        // ---- 14. new read weights ----
        for (int q = tid; q < RHEADS * MDIM; q += NT) {
            int r = q >> 9;
            rw[q] = sc[16 + 3 * r] * bwd[q] + sc[17 + 3 * r] * fwd[q] + sc[18 + 3 * r] * cw[q];
        }
        __syncthreads();

        // ---- 15. read vectors -> last_read (inp[256..]) ----
        {
            int pair = tid >> 2, q4 = tid & 3;     // pair < 256
            int r = pair >> 6, w_ = pair & 63;
            const float* rwr = rw + r * MDIM;
            float acc = 0.0f;
            int m0 = q4 << 7;
#pragma unroll 8
            for (int mm = m0; mm < m0 + 128; mm++) acc += rwr[mm] * mem[mm * 64 + w_];
#pragma unroll
            for (int o = 2; o; o >>= 1) acc += __shfl_down_sync(0xffffffffu, acc, o, 4);
            if (q4 == 0) inp[256 + pair] = acc;
        }
        __syncthreads();

        // ---- 16. output: y = [out, read_vecs] @ W_mem^T + b_mem ----
        {
            float* yrow = y_out + ((size_t)b * TT + t) * INDIM;
            const ulonglong2* v1 = (const ulonglong2*)outv;
            const ulonglong2* v2 = (const ulonglong2*)(inp + 256);
            for (int o = warp; o < INDIM; o += NWARP) {
                const ulonglong2* w2 = (const ulonglong2*)(W_mem + (size_t)o * 768);
                ull acc = 0;
#pragma unroll
                for (int kk = 0; kk < 6; kk++) {
                    int k = lane + (kk << 5);
                    ulonglong2 a = w2[k];
                    ulonglong2 p = (k < 128) ? v1[k] : v2[k - 128];
                    acc = fma2(a.x, p.x, acc);
                    acc = fma2(a.y, p.y, acc);
                }
                float2 f = upk2(acc);
                float s = warp_sum(f.x + f.y);
                if (!lane) yrow[o] = s + b_mem[o];
            }
        }
        __syncthreads();
    }
}

extern "C" void kernel_launch(void* const* d_in, const int* in_sizes, int n_in,
                              void* d_out, int out_size) {
    (void)in_sizes; (void)n_in; (void)out_size;
    const int SMEM_BYTES = 50656 * 4;  // 202624
    cudaFuncSetAttribute(dnc_kernel, cudaFuncAttributeMaxDynamicSharedMemorySize, SMEM_BYTES);
    dnc_kernel<<<BB, NT, SMEM_BYTES>>>(
        (const float*)d_in[0],
        (const float*)d_in[1], (const float*)d_in[2],
        (const float*)d_in[3], (const float*)d_in[4],
        (const float*)d_in[5], (const float*)d_in[6],
        (const float*)d_in[7], (const float*)d_in[8],
        (const float*)d_in[9], (const float*)d_in[10],
        (float*)d_out);
}